// round 15
// baseline (speedup 1.0000x reference)
#include <cuda_runtime.h>
#include <math.h>

#define DTc 1e-4f
#define LN_EPS 1e-5f
#define B_ 16
#define S_ 4096
#define D_ 256
#define N_ 16
#define CHUNK 64
#define NCHUNK (S_/CHUNK)   // 64
#define PADX 36             // 32 k-cols + 4 pad

// scratch (no cudaMalloc allowed)
__device__ float g_H[B_*S_*N_];          // 4 MB

typedef unsigned long long ull;

__device__ __forceinline__ void fma2(ull& d, ull a, ull b){
    asm("fma.rn.f32x2 %0, %1, %2, %0;" : "+l"(d) : "l"(a), "l"(b));
}
__device__ __forceinline__ ull mul2(ull a, ull b){
    ull r; asm("mul.rn.f32x2 %0, %1, %2;" : "=l"(r) : "l"(a), "l"(b)); return r;
}
__device__ __forceinline__ ull pack2(float v){
    ull r; asm("mov.b64 %0, {%1, %1};" : "=l"(r) : "f"(v)); return r;
}
__device__ __forceinline__ void unpk(float& lo, float& hi, ull v){
    asm("mov.b64 {%0, %1}, %2;" : "=f"(lo), "=f"(hi) : "l"(v));
}
__device__ __forceinline__ void cpa16(float* s, const float4* g){
    unsigned sa = (unsigned)__cvta_generic_to_shared(s);
    asm volatile("cp.async.ca.shared.global [%0], [%1], 16;" :: "r"(sa), "l"(g));
}

// ---------------------------------------------------------------------------
// K1: U = DT * x @ Bm^T for 256 rows (4 chunks). FFMA2 over k-parity pairs,
// cp.async double-buffered 32-col k-tiles, per-chunk local scans (h0=0).
// (identical to round-6 version: 33.7 us)
// ---------------------------------------------------------------------------
__global__ void __launch_bounds__(256,2) k1(const float* __restrict__ x,
                                            const float* __restrict__ A,
                                            const float* __restrict__ Bm){
    extern __shared__ float sm[];
    float* sx0 = sm;                       // 256*36
    float* sx1 = sm + 256*PADX;            // 256*36
    float* sw2 = sm + 2*256*PADX;          // [n][k] pad 260: 16*260
    float* su  = sw2 + 16*260;             // [row][n] pad 20: 256*20
    const int blk = blockIdx.x, b = blockIdx.y;
    const int tid = threadIdx.x;
    const int nt = tid & 3, tt = tid >> 2; // tt 0..63

    for (int i = tid; i < N_*D_; i += 256){
        int nn = i >> 8, k = i & 255;
        sw2[nn*260 + k] = DTc * Bm[i];
    }

    const float4* xg = (const float4*)(x + (size_t)(b*S_ + blk*256)*D_);

    ull acc[4][4];
    #pragma unroll
    for (int r = 0; r < 4; r++)
        #pragma unroll
        for (int i = 0; i < 4; i++) acc[r][i] = 0ull;

    #pragma unroll
    for (int j = 0; j < 8; j++){
        int i = tid + j*256;
        int t = i >> 3, q = i & 7;
        cpa16(sx0 + t*PADX + q*4, xg + (size_t)t*64 + q);
    }
    asm volatile("cp.async.commit_group;");

    #pragma unroll
    for (int kt = 0; kt < 8; kt++){
        float* cur = (kt & 1) ? sx1 : sx0;
        float* nxt = (kt & 1) ? sx0 : sx1;
        if (kt < 7){
            #pragma unroll
            for (int j = 0; j < 8; j++){
                int i = tid + j*256;
                int t = i >> 3, q = i & 7;
                cpa16(nxt + t*PADX + q*4, xg + (size_t)t*64 + (kt+1)*8 + q);
            }
            asm volatile("cp.async.commit_group;");
            asm volatile("cp.async.wait_group 1;");
        } else {
            asm volatile("cp.async.wait_group 0;");
        }
        __syncthreads();

        const ulonglong2* xr0 = (const ulonglong2*)(cur + (tt      )*PADX);
        const ulonglong2* xr1 = (const ulonglong2*)(cur + (tt +  64)*PADX);
        const ulonglong2* xr2 = (const ulonglong2*)(cur + (tt + 128)*PADX);
        const ulonglong2* xr3 = (const ulonglong2*)(cur + (tt + 192)*PADX);
        const ulonglong2* wr0 = (const ulonglong2*)(sw2 + (nt     )*260 + kt*32);
        const ulonglong2* wr1 = (const ulonglong2*)(sw2 + (nt +  4)*260 + kt*32);
        const ulonglong2* wr2 = (const ulonglong2*)(sw2 + (nt +  8)*260 + kt*32);
        const ulonglong2* wr3 = (const ulonglong2*)(sw2 + (nt + 12)*260 + kt*32);

        #pragma unroll
        for (int k4 = 0; k4 < 8; k4++){
            ulonglong2 xa = xr0[k4], xb = xr1[k4], xc = xr2[k4], xd = xr3[k4];
            ulonglong2 w0 = wr0[k4], w1 = wr1[k4], w2 = wr2[k4], w3 = wr3[k4];
            fma2(acc[0][0], xa.x, w0.x); fma2(acc[0][0], xa.y, w0.y);
            fma2(acc[0][1], xa.x, w1.x); fma2(acc[0][1], xa.y, w1.y);
            fma2(acc[0][2], xa.x, w2.x); fma2(acc[0][2], xa.y, w2.y);
            fma2(acc[0][3], xa.x, w3.x); fma2(acc[0][3], xa.y, w3.y);
            fma2(acc[1][0], xb.x, w0.x); fma2(acc[1][0], xb.y, w0.y);
            fma2(acc[1][1], xb.x, w1.x); fma2(acc[1][1], xb.y, w1.y);
            fma2(acc[1][2], xb.x, w2.x); fma2(acc[1][2], xb.y, w2.y);
            fma2(acc[1][3], xb.x, w3.x); fma2(acc[1][3], xb.y, w3.y);
            fma2(acc[2][0], xc.x, w0.x); fma2(acc[2][0], xc.y, w0.y);
            fma2(acc[2][1], xc.x, w1.x); fma2(acc[2][1], xc.y, w1.y);
            fma2(acc[2][2], xc.x, w2.x); fma2(acc[2][2], xc.y, w2.y);
            fma2(acc[2][3], xc.x, w3.x); fma2(acc[2][3], xc.y, w3.y);
            fma2(acc[3][0], xd.x, w0.x); fma2(acc[3][0], xd.y, w0.y);
            fma2(acc[3][1], xd.x, w1.x); fma2(acc[3][1], xd.y, w1.y);
            fma2(acc[3][2], xd.x, w2.x); fma2(acc[3][2], xd.y, w2.y);
            fma2(acc[3][3], xd.x, w3.x); fma2(acc[3][3], xd.y, w3.y);
        }
        __syncthreads();
    }

    #pragma unroll
    for (int r = 0; r < 4; r++)
        #pragma unroll
        for (int i = 0; i < 4; i++){
            float lo, hi;
            unpk(lo, hi, acc[r][i]);
            su[(tt + 64*r)*20 + (nt + 4*i)] = lo + hi;
        }
    __syncthreads();

    if (tid < 64){
        int n = tid & 15, cc = tid >> 4;
        float a = expf(-DTc*fabsf(A[n]));
        float h = 0.f;
        float* p = su + cc*64*20 + n;
        #pragma unroll 8
        for (int t = 0; t < CHUNK; t++){
            h = fmaf(a, h, p[t*20]);
            p[t*20] = h;
        }
    }
    __syncthreads();

    float* Hg = g_H + (size_t)(b*S_ + blk*256)*N_;
    #pragma unroll
    for (int j = 0; j < 16; j++){
        int i = tid + j*256;
        Hg[i] = su[(i>>4)*20 + (i&15)];
    }
}

// ---------------------------------------------------------------------------
// K3: block = 128 rows (2 chunks), 512 thr = 16 warps; warp owns 8 rows in
// two 4-row passes (proven 32-reg acc tile). h stored PRE-DUPLICATED as
// (h,h) ull pairs -> hot loop has zero pack ops: per n = 2 bcast LDS.128 (h)
// + 2 LDS.128 (C) + 16 FFMA2. In-block carry, fixup, fused LayerNorm.
// ---------------------------------------------------------------------------
__global__ void __launch_bounds__(512,2) k3(const float* __restrict__ x,
                                            const float* __restrict__ A,
                                            const float* __restrict__ Cm,
                                            const float* __restrict__ Dv,
                                            const float* __restrict__ gamma,
                                            const float* __restrict__ beta,
                                            float* __restrict__ out){
    __shared__ __align__(16) float sC[N_*260];     // [n][d] pad 260
    __shared__ __align__(16) ull   shd[N_*132];    // [n][t] dup pairs (t 0..127)
    __shared__ __align__(16) float sDv[D_], sg[D_], sb[D_];
    __shared__ float scarr[2][N_];
    const int blk = blockIdx.x, b = blockIdx.y;    // 32 x 16 = 512 blocks
    const int tid = threadIdx.x;
    const int warp = tid >> 5, lane = tid & 31;
    const int row0 = blk*128;
    const int cb = 2*blk;

    // in-block carry for chunks cb, cb+1 (threads 0..15)
    if (tid < 16){
        const int n = tid;
        float a64 = expf(-DTc*fabsf(A[n])*64.f);
        float carry = 0.f;
        for (int c0 = 0; c0 < cb; c0 += 16){
            float v[16];
            #pragma unroll
            for (int i = 0; i < 16; i++)
                if (c0 + i < cb)
                    v[i] = g_H[((size_t)b*S_ + (c0+i)*CHUNK + (CHUNK-1))*N_ + n];
            #pragma unroll
            for (int i = 0; i < 16; i++)
                if (c0 + i < cb)
                    carry = fmaf(a64, carry, v[i]);
        }
        scarr[0][n] = carry;
        float L0 = g_H[((size_t)b*S_ + cb*CHUNK + (CHUNK-1))*N_ + n];
        scarr[1][n] = fmaf(a64, carry, L0);
    }

    // stage C (transposed), Dv/gamma/beta, h (duplicated pairs)
    for (int i = tid; i < D_*N_; i += 512){
        int d = i >> 4, n = i & 15;
        sC[n*260 + d] = Cm[i];
    }
    for (int i = tid; i < D_; i += 512){ sDv[i]=Dv[i]; sg[i]=gamma[i]; sb[i]=beta[i]; }
    {
        const float* Hg = g_H + (size_t)(b*S_ + row0)*N_;
        #pragma unroll
        for (int j = 0; j < 4; j++){
            int i = tid + j*512;            // 2048 elems
            int t = i >> 4, n = i & 15;
            shd[n*132 + t] = pack2(Hg[i]);
        }
    }
    __syncthreads();

    // fixup: 256 threads, (n, seg of 8 rows): h += a^{tl+1} * carry_chunk
    if (tid < 256){
        int n = tid & 15, seg = tid >> 4;   // seg 0..15
        int cc  = seg >> 3;                 // chunk within block
        int tl0 = (seg & 7)*8;              // local t offset in chunk
        float absA = fabsf(A[n]);
        float a = expf(-DTc*absA);
        float p = scarr[cc][n] * expf(-DTc*absA*(float)tl0);
        ull* rowp = shd + n*132 + seg*8;
        #pragma unroll
        for (int i = 0; i < 8; i++){
            p *= a;
            float lo, hi;
            unpk(lo, hi, rowp[i]);
            rowp[i] = pack2(lo + p);
        }
    }
    __syncthreads();

    // GEMM + LN: warp owns rows warp*8 .. +7, two passes of 4
    const int d0 = 4*lane;
    #pragma unroll
    for (int pass = 0; pass < 2; pass++){
        const int t0 = warp*8 + pass*4;
        const float* xr = x + (size_t)(b*S_ + row0 + t0)*D_;

        ull y2[4][2][2];
        #pragma unroll
        for (int r = 0; r < 4; r++)
            #pragma unroll
            for (int j = 0; j < 2; j++){
                int d = d0 + 128*j;
                float4 xv = *(const float4*)(xr + r*D_ + d);
                ulonglong2 xp = *(ulonglong2*)&xv;
                ulonglong2 dv = *(const ulonglong2*)(sDv + d);
                y2[r][j][0] = mul2(xp.x, dv.x);
                y2[r][j][1] = mul2(xp.y, dv.y);
            }

        #pragma unroll
        for (int n = 0; n < 16; n++){
            const ull* hp = shd + n*132 + t0;
            ulonglong2 h01 = *(const ulonglong2*)(hp    );   // (h0,h0),(h1,h1)
            ulonglong2 h23 = *(const ulonglong2*)(hp + 2);   // (h2,h2),(h3,h3)
            ulonglong2 c0 = *(const ulonglong2*)(sC + n*260 + d0);
            ulonglong2 c1 = *(const ulonglong2*)(sC + n*260 + d0 + 128);
            fma2(y2[0][0][0], h01.x, c0.x); fma2(y2[0][0][1], h01.x, c0.y);
            fma2(y2[0][1][0], h01.x, c1.x); fma2(y2[0][1][1], h01.x, c1.y);
            fma2(y2[1][0][0], h01.y, c0.x); fma2(y2[1][0][1], h01.y, c0.y);
            fma2(y2[1][1][0], h01.y, c1.x); fma2(y2[1][1][1], h01.y, c1.y);
            fma2(y2[2][0][0], h23.x, c0.x); fma2(y2[2][0][1], h23.x, c0.y);
            fma2(y2[2][1][0], h23.x, c1.x); fma2(y2[2][1][1], h23.x, c1.y);
            fma2(y2[3][0][0], h23.y, c0.x); fma2(y2[3][0][1], h23.y, c0.y);
            fma2(y2[3][1][0], h23.y, c1.x); fma2(y2[3][1][1], h23.y, c1.y);
        }

        float* og = out + (size_t)(b*S_ + row0 + t0)*D_;
        #pragma unroll
        for (int r = 0; r < 4; r++){
            float yv[8];
            float s = 0.f, s2 = 0.f;
            #pragma unroll
            for (int j = 0; j < 2; j++)
                #pragma unroll
                for (int p2 = 0; p2 < 2; p2++){
                    float lo, hi;
                    unpk(lo, hi, y2[r][j][p2]);
                    lo = fminf(fmaxf(lo, -10.f), 10.f);
                    hi = fminf(fmaxf(hi, -10.f), 10.f);
                    yv[j*4 + p2*2]     = lo;
                    yv[j*4 + p2*2 + 1] = hi;
                    s += lo + hi;
                    s2 = fmaf(lo, lo, s2);
                    s2 = fmaf(hi, hi, s2);
                }
            #pragma unroll
            for (int o = 16; o; o >>= 1){
                s  += __shfl_xor_sync(0xffffffffu, s,  o);
                s2 += __shfl_xor_sync(0xffffffffu, s2, o);
            }
            float mu   = s * (1.f/256.f);
            float var  = fmaf(s2, 1.f/256.f, -mu*mu);
            float rinv = rsqrtf(var + LN_EPS);
            #pragma unroll
            for (int j = 0; j < 2; j++){
                int d = d0 + 128*j;
                float4 gg = *(const float4*)(sg + d);
                float4 bb = *(const float4*)(sb + d);
                float4 o4;
                o4.x = fmaf((yv[j*4+0]-mu)*rinv, gg.x, bb.x);
                o4.y = fmaf((yv[j*4+1]-mu)*rinv, gg.y, bb.y);
                o4.z = fmaf((yv[j*4+2]-mu)*rinv, gg.z, bb.z);
                o4.w = fmaf((yv[j*4+3]-mu)*rinv, gg.w, bb.w);
                *(float4*)(og + r*D_ + d) = o4;
            }
        }
    }
}

// ---------------------------------------------------------------------------
extern "C" void kernel_launch(void* const* d_in, const int* in_sizes, int n_in,
                              void* d_out, int out_size){
    const float* x     = (const float*)d_in[0];
    const float* A     = (const float*)d_in[1];
    const float* Bm    = (const float*)d_in[2];
    const float* Cm    = (const float*)d_in[3];
    const float* Dv    = (const float*)d_in[4];
    const float* gamma = (const float*)d_in[5];
    const float* beta  = (const float*)d_in[6];
    float* out = (float*)d_out;

    size_t smem1 = (size_t)(2*256*PADX + 16*260 + 256*20) * sizeof(float); // 110848 B
    cudaFuncSetAttribute(k1, cudaFuncAttributeMaxDynamicSharedMemorySize, (int)smem1);

    dim3 grid1(S_/256, B_);     // 16 x 16 = 256 blocks
    dim3 grid3(S_/128, B_);     // 32 x 16 = 512 blocks
    k1<<<grid1, 256, smem1>>>(x, A, Bm);
    k3<<<grid3, 512>>>(x, A, Cm, Dv, gamma, beta, out);
}

// round 16
// speedup vs baseline: 2.0865x; 2.0865x over previous
#include <cuda_runtime.h>
#include <math.h>

#define DTc 1e-4f
#define LN_EPS 1e-5f
#define B_ 16
#define S_ 4096
#define D_ 256
#define N_ 16
#define CHUNK 64
#define NCHUNK (S_/CHUNK)   // 64
#define PADX 36             // 32 k-cols + 4 pad

// scratch (no cudaMalloc allowed)
__device__ float g_H[B_*S_*N_];          // 4 MB

typedef unsigned long long ull;

__device__ __forceinline__ void fma2(ull& d, ull a, ull b){
    asm("fma.rn.f32x2 %0, %1, %2, %0;" : "+l"(d) : "l"(a), "l"(b));
}
__device__ __forceinline__ ull mul2(ull a, ull b){
    ull r; asm("mul.rn.f32x2 %0, %1, %2;" : "=l"(r) : "l"(a), "l"(b)); return r;
}
__device__ __forceinline__ ull pack2(float v){
    ull r; asm("mov.b64 %0, {%1, %1};" : "=l"(r) : "f"(v)); return r;
}
__device__ __forceinline__ void unpk(float& lo, float& hi, ull v){
    asm("mov.b64 {%0, %1}, %2;" : "=f"(lo), "=f"(hi) : "l"(v));
}
__device__ __forceinline__ void cpa16(float* s, const float4* g){
    unsigned sa = (unsigned)__cvta_generic_to_shared(s);
    asm volatile("cp.async.ca.shared.global [%0], [%1], 16;" :: "r"(sa), "l"(g));
}

// ---------------------------------------------------------------------------
// K1: U = DT * x @ Bm^T for 256 rows (4 chunks). FFMA2 over k-parity pairs,
// cp.async double-buffered 32-col k-tiles, per-chunk local scans (h0=0).
// (identical to round-6 version: 33.7 us)
// ---------------------------------------------------------------------------
__global__ void __launch_bounds__(256,2) k1(const float* __restrict__ x,
                                            const float* __restrict__ A,
                                            const float* __restrict__ Bm){
    extern __shared__ float sm[];
    float* sx0 = sm;                       // 256*36
    float* sx1 = sm + 256*PADX;            // 256*36
    float* sw2 = sm + 2*256*PADX;          // [n][k] pad 260: 16*260
    float* su  = sw2 + 16*260;             // [row][n] pad 20: 256*20
    const int blk = blockIdx.x, b = blockIdx.y;
    const int tid = threadIdx.x;
    const int nt = tid & 3, tt = tid >> 2; // tt 0..63

    for (int i = tid; i < N_*D_; i += 256){
        int nn = i >> 8, k = i & 255;
        sw2[nn*260 + k] = DTc * Bm[i];
    }

    const float4* xg = (const float4*)(x + (size_t)(b*S_ + blk*256)*D_);

    ull acc[4][4];
    #pragma unroll
    for (int r = 0; r < 4; r++)
        #pragma unroll
        for (int i = 0; i < 4; i++) acc[r][i] = 0ull;

    #pragma unroll
    for (int j = 0; j < 8; j++){
        int i = tid + j*256;
        int t = i >> 3, q = i & 7;
        cpa16(sx0 + t*PADX + q*4, xg + (size_t)t*64 + q);
    }
    asm volatile("cp.async.commit_group;");

    #pragma unroll
    for (int kt = 0; kt < 8; kt++){
        float* cur = (kt & 1) ? sx1 : sx0;
        float* nxt = (kt & 1) ? sx0 : sx1;
        if (kt < 7){
            #pragma unroll
            for (int j = 0; j < 8; j++){
                int i = tid + j*256;
                int t = i >> 3, q = i & 7;
                cpa16(nxt + t*PADX + q*4, xg + (size_t)t*64 + (kt+1)*8 + q);
            }
            asm volatile("cp.async.commit_group;");
            asm volatile("cp.async.wait_group 1;");
        } else {
            asm volatile("cp.async.wait_group 0;");
        }
        __syncthreads();

        const ulonglong2* xr0 = (const ulonglong2*)(cur + (tt      )*PADX);
        const ulonglong2* xr1 = (const ulonglong2*)(cur + (tt +  64)*PADX);
        const ulonglong2* xr2 = (const ulonglong2*)(cur + (tt + 128)*PADX);
        const ulonglong2* xr3 = (const ulonglong2*)(cur + (tt + 192)*PADX);
        const ulonglong2* wr0 = (const ulonglong2*)(sw2 + (nt     )*260 + kt*32);
        const ulonglong2* wr1 = (const ulonglong2*)(sw2 + (nt +  4)*260 + kt*32);
        const ulonglong2* wr2 = (const ulonglong2*)(sw2 + (nt +  8)*260 + kt*32);
        const ulonglong2* wr3 = (const ulonglong2*)(sw2 + (nt + 12)*260 + kt*32);

        #pragma unroll
        for (int k4 = 0; k4 < 8; k4++){
            ulonglong2 xa = xr0[k4], xb = xr1[k4], xc = xr2[k4], xd = xr3[k4];
            ulonglong2 w0 = wr0[k4], w1 = wr1[k4], w2 = wr2[k4], w3 = wr3[k4];
            fma2(acc[0][0], xa.x, w0.x); fma2(acc[0][0], xa.y, w0.y);
            fma2(acc[0][1], xa.x, w1.x); fma2(acc[0][1], xa.y, w1.y);
            fma2(acc[0][2], xa.x, w2.x); fma2(acc[0][2], xa.y, w2.y);
            fma2(acc[0][3], xa.x, w3.x); fma2(acc[0][3], xa.y, w3.y);
            fma2(acc[1][0], xb.x, w0.x); fma2(acc[1][0], xb.y, w0.y);
            fma2(acc[1][1], xb.x, w1.x); fma2(acc[1][1], xb.y, w1.y);
            fma2(acc[1][2], xb.x, w2.x); fma2(acc[1][2], xb.y, w2.y);
            fma2(acc[1][3], xb.x, w3.x); fma2(acc[1][3], xb.y, w3.y);
            fma2(acc[2][0], xc.x, w0.x); fma2(acc[2][0], xc.y, w0.y);
            fma2(acc[2][1], xc.x, w1.x); fma2(acc[2][1], xc.y, w1.y);
            fma2(acc[2][2], xc.x, w2.x); fma2(acc[2][2], xc.y, w2.y);
            fma2(acc[2][3], xc.x, w3.x); fma2(acc[2][3], xc.y, w3.y);
            fma2(acc[3][0], xd.x, w0.x); fma2(acc[3][0], xd.y, w0.y);
            fma2(acc[3][1], xd.x, w1.x); fma2(acc[3][1], xd.y, w1.y);
            fma2(acc[3][2], xd.x, w2.x); fma2(acc[3][2], xd.y, w2.y);
            fma2(acc[3][3], xd.x, w3.x); fma2(acc[3][3], xd.y, w3.y);
        }
        __syncthreads();
    }

    #pragma unroll
    for (int r = 0; r < 4; r++)
        #pragma unroll
        for (int i = 0; i < 4; i++){
            float lo, hi;
            unpk(lo, hi, acc[r][i]);
            su[(tt + 64*r)*20 + (nt + 4*i)] = lo + hi;
        }
    __syncthreads();

    if (tid < 64){
        int n = tid & 15, cc = tid >> 4;
        float a = expf(-DTc*fabsf(A[n]));
        float h = 0.f;
        float* p = su + cc*64*20 + n;
        #pragma unroll 8
        for (int t = 0; t < CHUNK; t++){
            h = fmaf(a, h, p[t*20]);
            p[t*20] = h;
        }
    }
    __syncthreads();

    float* Hg = g_H + (size_t)(b*S_ + blk*256)*N_;
    #pragma unroll
    for (int j = 0; j < 16; j++){
        int i = tid + j*256;
        Hg[i] = su[(i>>4)*20 + (i&15)];
    }
}

// ---------------------------------------------------------------------------
// K3: R6 structure (grid 1024, block = ONE 64-row chunk, 512 thr, warp owns
// 4 rows, single pass) with h PRE-DUPLICATED as (h,h) ull pairs in smem:
// hot loop per n = 2 bcast LDS.128 (h) + 2 LDS.128 (C) + 16 FFMA2, zero packs.
// In-block carry (threads 0..15), fixup, clip, fused LayerNorm.
// ---------------------------------------------------------------------------
__global__ void __launch_bounds__(512,2) k3(const float* __restrict__ x,
                                            const float* __restrict__ A,
                                            const float* __restrict__ Cm,
                                            const float* __restrict__ Dv,
                                            const float* __restrict__ gamma,
                                            const float* __restrict__ beta,
                                            float* __restrict__ out){
    __shared__ __align__(16) float sC[N_*260];     // [n][d] pad 260
    __shared__ __align__(16) ull   shd[N_*68];     // [n][t] dup pairs (t 0..63)
    __shared__ __align__(16) float sDv[D_], sg[D_], sb[D_];
    __shared__ float scarr[N_];
    const int chunk = blockIdx.x, b = blockIdx.y;  // 64 x 16 = 1024 blocks
    const int tid = threadIdx.x;
    const int warp = tid >> 5, lane = tid & 31;
    const int t0 = warp * 4;

    // hoisted x prefetch (before any barrier)
    const float* xr = x + (size_t)(b*S_ + chunk*CHUNK + t0)*D_;
    const int d0 = 4*lane;
    float4 xv[4][2];
    #pragma unroll
    for (int r = 0; r < 4; r++)
        #pragma unroll
        for (int j = 0; j < 2; j++)
            xv[r][j] = *(const float4*)(xr + r*D_ + d0 + 128*j);

    // in-block carry for this chunk (threads 0..15), overlapped with staging
    if (tid < 16){
        const int n = tid;
        float a64 = expf(-DTc*fabsf(A[n])*64.f);
        float carry = 0.f;
        for (int c0 = 0; c0 < chunk; c0 += 16){
            float v[16];
            #pragma unroll
            for (int i = 0; i < 16; i++)
                if (c0 + i < chunk)
                    v[i] = g_H[((size_t)b*S_ + (c0+i)*CHUNK + (CHUNK-1))*N_ + n];
            #pragma unroll
            for (int i = 0; i < 16; i++)
                if (c0 + i < chunk)
                    carry = fmaf(a64, carry, v[i]);
        }
        scarr[n] = carry;
    }

    for (int i = tid; i < D_*N_; i += 512){
        int d = i >> 4, n = i & 15;
        sC[n*260 + d] = Cm[i];        // Cm[d][n]
    }
    for (int i = tid; i < D_; i += 512){ sDv[i]=Dv[i]; sg[i]=gamma[i]; sb[i]=beta[i]; }
    {
        const float* Hg = g_H + (size_t)(b*S_ + chunk*CHUNK)*N_;
        #pragma unroll
        for (int j = 0; j < 2; j++){
            int i = tid + j*512;           // 1024 elems
            int t = i >> 4, n = i & 15;
            shd[n*68 + t] = pack2(Hg[i]);
        }
    }
    __syncthreads();

    // fixup: 64 threads, 16-row segments: h += a^{tl+1} * carry
    if (tid < 64){
        int n = tid & 15, seg = tid >> 4;
        float absA = fabsf(A[n]);
        float a = expf(-DTc*absA);
        float p = scarr[n] * expf(-DTc*absA*(float)(seg*16));
        ull* row = shd + n*68 + seg*16;
        #pragma unroll
        for (int tl = 0; tl < 16; tl++){
            p *= a;
            float lo, hi;
            unpk(lo, hi, row[tl]);
            row[tl] = pack2(lo + p);
        }
    }
    __syncthreads();

    // y = x*Dv (f32x2)
    ull y2[4][2][2];
    #pragma unroll
    for (int r = 0; r < 4; r++)
        #pragma unroll
        for (int j = 0; j < 2; j++){
            int d = d0 + 128*j;
            ulonglong2 xp = *(ulonglong2*)&xv[r][j];
            ulonglong2 dv = *(const ulonglong2*)(sDv + d);
            y2[r][j][0] = mul2(xp.x, dv.x);
            y2[r][j][1] = mul2(xp.y, dv.y);
        }

    // GEMM: 16 n, zero-pack hot loop
    #pragma unroll
    for (int n = 0; n < 16; n++){
        const ull* hp = shd + n*68 + t0;
        ulonglong2 h01 = *(const ulonglong2*)(hp    );   // (h0,h0),(h1,h1)
        ulonglong2 h23 = *(const ulonglong2*)(hp + 2);   // (h2,h2),(h3,h3)
        ulonglong2 c0 = *(const ulonglong2*)(sC + n*260 + d0);
        ulonglong2 c1 = *(const ulonglong2*)(sC + n*260 + d0 + 128);
        fma2(y2[0][0][0], h01.x, c0.x); fma2(y2[0][0][1], h01.x, c0.y);
        fma2(y2[0][1][0], h01.x, c1.x); fma2(y2[0][1][1], h01.x, c1.y);
        fma2(y2[1][0][0], h01.y, c0.x); fma2(y2[1][0][1], h01.y, c0.y);
        fma2(y2[1][1][0], h01.y, c1.x); fma2(y2[1][1][1], h01.y, c1.y);
        fma2(y2[2][0][0], h23.x, c0.x); fma2(y2[2][0][1], h23.x, c0.y);
        fma2(y2[2][1][0], h23.x, c1.x); fma2(y2[2][1][1], h23.x, c1.y);
        fma2(y2[3][0][0], h23.y, c0.x); fma2(y2[3][0][1], h23.y, c0.y);
        fma2(y2[3][1][0], h23.y, c1.x); fma2(y2[3][1][1], h23.y, c1.y);
    }

    float* og = out + (size_t)(b*S_ + chunk*CHUNK + t0)*D_;
    #pragma unroll
    for (int r = 0; r < 4; r++){
        float yv[8];
        float s = 0.f, s2 = 0.f;
        #pragma unroll
        for (int j = 0; j < 2; j++)
            #pragma unroll
            for (int p2 = 0; p2 < 2; p2++){
                float lo, hi;
                unpk(lo, hi, y2[r][j][p2]);
                lo = fminf(fmaxf(lo, -10.f), 10.f);
                hi = fminf(fmaxf(hi, -10.f), 10.f);
                yv[j*4 + p2*2]     = lo;
                yv[j*4 + p2*2 + 1] = hi;
                s += lo + hi;
                s2 = fmaf(lo, lo, s2);
                s2 = fmaf(hi, hi, s2);
            }
        #pragma unroll
        for (int o = 16; o; o >>= 1){
            s  += __shfl_xor_sync(0xffffffffu, s,  o);
            s2 += __shfl_xor_sync(0xffffffffu, s2, o);
        }
        float mu   = s * (1.f/256.f);
        float var  = fmaf(s2, 1.f/256.f, -mu*mu);
        float rinv = rsqrtf(var + LN_EPS);
        #pragma unroll
        for (int j = 0; j < 2; j++){
            int d = d0 + 128*j;
            float4 gg = *(const float4*)(sg + d);
            float4 bb = *(const float4*)(sb + d);
            float4 o4;
            o4.x = fmaf((yv[j*4+0]-mu)*rinv, gg.x, bb.x);
            o4.y = fmaf((yv[j*4+1]-mu)*rinv, gg.y, bb.y);
            o4.z = fmaf((yv[j*4+2]-mu)*rinv, gg.z, bb.z);
            o4.w = fmaf((yv[j*4+3]-mu)*rinv, gg.w, bb.w);
            *(float4*)(og + r*D_ + d) = o4;
        }
    }
}

// ---------------------------------------------------------------------------
extern "C" void kernel_launch(void* const* d_in, const int* in_sizes, int n_in,
                              void* d_out, int out_size){
    const float* x     = (const float*)d_in[0];
    const float* A     = (const float*)d_in[1];
    const float* Bm    = (const float*)d_in[2];
    const float* Cm    = (const float*)d_in[3];
    const float* Dv    = (const float*)d_in[4];
    const float* gamma = (const float*)d_in[5];
    const float* beta  = (const float*)d_in[6];
    float* out = (float*)d_out;

    size_t smem1 = (size_t)(2*256*PADX + 16*260 + 256*20) * sizeof(float); // 110848 B
    cudaFuncSetAttribute(k1, cudaFuncAttributeMaxDynamicSharedMemorySize, (int)smem1);

    dim3 grid1(S_/256, B_);     // 16 x 16 = 256 blocks
    dim3 grid3(NCHUNK, B_);     // 64 x 16 = 1024 blocks
    k1<<<grid1, 256, smem1>>>(x, A, Bm);
    k3<<<grid3, 512>>>(x, A, Cm, Dv, gamma, beta, out);
}